// round 14
// baseline (speedup 1.0000x reference)
#include <cuda_runtime.h>
#include <cuda_bf16.h>
#include <cuda_fp16.h>
#include <cstdint>

// Problem constants
#define BB 2
#define TT 2048
#define DD 1024
#define HH 16
#define HD 64
#define M_ROWS 4096
#define QKV_N 3072
#define KDIM 1024

// ---------------------------------------------------------------------------
// Device-global scratch (allocation-free rule)
// ---------------------------------------------------------------------------
__device__ __half g_X16[(size_t)M_ROWS * KDIM];
__device__ __half g_Wq16[(size_t)QKV_N * KDIM];   // q rows pre-scaled by 1/8
__device__ __half g_Wo16[(size_t)DD * DD];
__device__ __half g_qkv16[(size_t)M_ROWS * QKV_N];  // q | k | v fp16
__device__ __half g_z16[(size_t)M_ROWS * DD];       // z fp16

// ---------------------------------------------------------------------------
// PTX helpers (baseline ISA: mma.sync sm_80, ldmatrix sm_75, cp.async sm_80)
// ---------------------------------------------------------------------------
__device__ __forceinline__ uint32_t smem_u32(const void* p) {
    uint32_t a;
    asm("{ .reg .u64 t; cvta.to.shared.u64 t, %1; cvt.u32.u64 %0, t; }"
        : "=r"(a) : "l"(p));
    return a;
}

__device__ __forceinline__ void cp16(uint32_t dst, const void* src) {
    asm volatile("cp.async.cg.shared.global [%0], [%1], 16;"
                 :: "r"(dst), "l"(src));
}
#define CP_COMMIT() asm volatile("cp.async.commit_group;" ::: "memory")
#define CP_WAIT1()  asm volatile("cp.async.wait_group 1;" ::: "memory")
#define CP_WAIT0()  asm volatile("cp.async.wait_group 0;" ::: "memory")

__device__ __forceinline__ void ldsm4(uint32_t& r0, uint32_t& r1, uint32_t& r2,
                                      uint32_t& r3, uint32_t addr) {
    asm volatile("ldmatrix.sync.aligned.m8n8.x4.shared.b16 {%0,%1,%2,%3}, [%4];"
                 : "=r"(r0), "=r"(r1), "=r"(r2), "=r"(r3) : "r"(addr));
}
__device__ __forceinline__ void ldsm4t(uint32_t& r0, uint32_t& r1, uint32_t& r2,
                                       uint32_t& r3, uint32_t addr) {
    asm volatile("ldmatrix.sync.aligned.m8n8.x4.trans.shared.b16 {%0,%1,%2,%3}, [%4];"
                 : "=r"(r0), "=r"(r1), "=r"(r2), "=r"(r3) : "r"(addr));
}

__device__ __forceinline__ void mma_f16(float* d, uint32_t a0, uint32_t a1,
                                        uint32_t a2, uint32_t a3,
                                        uint32_t b0, uint32_t b1)
{
    asm volatile(
        "mma.sync.aligned.m16n8k16.row.col.f32.f16.f16.f32 "
        "{%0,%1,%2,%3}, {%4,%5,%6,%7}, {%8,%9}, {%0,%1,%2,%3};"
        : "+f"(d[0]), "+f"(d[1]), "+f"(d[2]), "+f"(d[3])
        : "r"(a0), "r"(a1), "r"(a2), "r"(a3), "r"(b0), "r"(b1));
}

__device__ __forceinline__ uint32_t packh2(float x, float y)
{
    __half2 h = __floats2half2_rn(x, y);
    return *(uint32_t*)&h;
}

// ---------------------------------------------------------------------------
// Merged conversion kernel: X, Wqkv (q-rows pre-scaled by 1/8), Wout -> fp16
// ---------------------------------------------------------------------------
#define N4_X  (M_ROWS * KDIM / 4)       // 1048576
#define N4_WQ (QKV_N * KDIM / 4)        // 786432
#define N4_WO (DD * DD / 4)             // 262144
#define N4_QS (DD * KDIM / 4)           // 262144 (q out-feature rows of Wqkv)
#define N4_ALL (N4_X + N4_WQ + N4_WO)   // 2097152

__global__ void convert_all(const float* __restrict__ X,
                            const float* __restrict__ Wqkv,
                            const float* __restrict__ Wout,
                            __half* __restrict__ X16,
                            __half* __restrict__ Wq16,
                            __half* __restrict__ Wo16)
{
    const int i = blockIdx.x * blockDim.x + threadIdx.x;
    if (i < N4_X) {
        float4 v = ((const float4*)X)[i];
        ((uint2*)X16)[i] = make_uint2(packh2(v.x, v.y), packh2(v.z, v.w));
    } else if (i < N4_X + N4_WQ) {
        const int j = i - N4_X;
        float4 v = ((const float4*)Wqkv)[j];
        const float sc = (j < N4_QS) ? 0.125f : 1.0f;   // fold 1/sqrt(HD) into q
        ((uint2*)Wq16)[j] = make_uint2(packh2(v.x * sc, v.y * sc),
                                       packh2(v.z * sc, v.w * sc));
    } else {
        const int j = i - N4_X - N4_WQ;
        float4 v = ((const float4*)Wout)[j];
        ((uint2*)Wo16)[j] = make_uint2(packh2(v.x, v.y), packh2(v.z, v.w));
    }
}

// ===========================================================================
// fp16 single-pass GEMM NT: C = A16 * B16^T, K=1024.
// CTA 128x128, K-chunk 32 (the empirically best MMA-feeding shape, R9),
// 3-stage cp.async pipeline (2 chunks in flight), ONE __syncthreads/chunk,
// ldmatrix fragments, 2 CTAs/SM. HALF_OUT=true -> fp16 out; else fp32 out.
// smem: 3 stages x (A,B [128][40] f16) = 61440 B.
// ===========================================================================
#define G_ARR 10240                  // 128*40*2 bytes
#define G_STAGE (2 * G_ARR)          // 20480
#define G_SMEM (3 * G_STAGE)         // 61440
#define G_NCHUNK (KDIM / 32)         // 32

template<bool HALF_OUT>
__global__ __launch_bounds__(256, 2) void gemm_f16(
    const __half* __restrict__ Ag, const __half* __restrict__ Bg,
    float* __restrict__ Cf, __half* __restrict__ Chf, int N)
{
    extern __shared__ char hsm[];
    const uint32_t sb0 = smem_u32(hsm);

    const int tid = threadIdx.x;
    const int wid = tid >> 5;
    const int lid = tid & 31;
    const int g   = lid >> 2;
    const int tig = lid & 3;
    const int wm  = wid & 1;
    const int wn  = wid >> 1;
    const int bY  = blockIdx.y * 128;
    const int bX  = blockIdx.x * 128;

    const uint32_t aOff = (uint32_t)(wm * 64 + (lid & 15)) * 80
                        + ((lid & 16) ? 16u : 0u);
    const uint32_t bOff = (uint32_t)(wn * 32 + (lid & 7) + ((lid & 16) ? 8 : 0)) * 80
                        + ((lid & 8) ? 16u : 0u);

    // loader: per chunk, 2 cp16 per thread per matrix (128 rows x 64 B)
    const int ldRow0 = tid >> 2;         // j=0 rows 0..63
    const int ldCh   = (tid & 3) * 16;   // 16B segment within the 64B row
#define G_LOAD(c, st) do {                                                     \
        const uint32_t sb_ = sb0 + (st) * G_STAGE;                             \
        _Pragma("unroll")                                                      \
        for (int j_ = 0; j_ < 2; j_++) {                                       \
            const int row_ = ldRow0 + 64 * j_;                                 \
            const uint32_t d_ = (uint32_t)row_ * 80 + ldCh;                    \
            cp16(sb_ + d_,         Ag + (size_t)(bY + row_) * KDIM + (c) * 32 + ldCh / 2); \
            cp16(sb_ + G_ARR + d_, Bg + (size_t)(bX + row_) * KDIM + (c) * 32 + ldCh / 2); \
        }                                                                      \
    } while (0)

    float acc[4][4][4];
#pragma unroll
    for (int mi = 0; mi < 4; mi++)
#pragma unroll
        for (int ni = 0; ni < 4; ni++)
#pragma unroll
            for (int r = 0; r < 4; r++) acc[mi][ni][r] = 0.f;

    G_LOAD(0, 0); CP_COMMIT();
    G_LOAD(1, 1); CP_COMMIT();

    int st = 2;          // next stage to fill
    for (int c = 0; c < G_NCHUNK; c++) {
        if (c < G_NCHUNK - 1) { CP_WAIT1(); } else { CP_WAIT0(); }
        __syncthreads();   // chunk c visible to all; prior compute of c-1 done

        // issue next load into the stage freed by chunk c-1
        if (c + 2 < G_NCHUNK) {
            G_LOAD(c + 2, st);
            CP_COMMIT();
            st = (st == 2) ? 0 : st + 1;
        }

        const uint32_t sb = sb0 + (c % 3) * G_STAGE;
#pragma unroll
        for (int k16 = 0; k16 < 2; k16++) {
            const uint32_t kb = k16 * 32;
            const uint32_t bBase = sb + G_ARR + bOff + kb;
            uint32_t bf_[2][4];
            ldsm4(bf_[0][0], bf_[0][1], bf_[0][2], bf_[0][3], bBase);
            ldsm4(bf_[1][0], bf_[1][1], bf_[1][2], bf_[1][3], bBase + 16 * 80);
#pragma unroll
            for (int mi = 0; mi < 4; mi++) {
                uint32_t a0, a1, a2, a3;
                ldsm4(a0, a1, a2, a3, sb + aOff + kb + (uint32_t)mi * 16 * 80);
#pragma unroll
                for (int ni = 0; ni < 4; ni++)
                    mma_f16(acc[mi][ni], a0, a1, a2, a3,
                            bf_[ni >> 1][(ni & 1) * 2],
                            bf_[ni >> 1][(ni & 1) * 2 + 1]);
            }
        }
    }

#pragma unroll
    for (int mi = 0; mi < 4; mi++) {
        const int r0 = bY + wm * 64 + mi * 16 + g;
#pragma unroll
        for (int ni = 0; ni < 4; ni++) {
            const int c0 = bX + wn * 32 + ni * 8 + tig * 2;
            if (HALF_OUT) {
                *(uint32_t*)&Chf[(size_t)r0 * N + c0] =
                    packh2(acc[mi][ni][0], acc[mi][ni][1]);
                *(uint32_t*)&Chf[(size_t)(r0 + 8) * N + c0] =
                    packh2(acc[mi][ni][2], acc[mi][ni][3]);
            } else {
                float2 v0; v0.x = acc[mi][ni][0]; v0.y = acc[mi][ni][1];
                float2 v1; v1.x = acc[mi][ni][2]; v1.y = acc[mi][ni][3];
                *(float2*)(Cf + (size_t)r0 * N + c0)       = v0;
                *(float2*)(Cf + (size_t)(r0 + 8) * N + c0) = v1;
            }
        }
    }
#undef G_LOAD
}

// ===========================================================================
// Flash attention (unchanged from passing round-13 kernel): all fp16
// single-pass, paired q-tiles (qt = 15-i then i -> 34 kv units per CTA),
// grid 8x16x2 = one balanced wave at 2 CTAs/SM. Q pre-scaled by 1/8.
// smem: Q[128][72] f16 + 2 stages x (K,V [64][72] f16) = 55296 B.
// ===========================================================================
#define F_QARR 18432                 // 128*72*2
#define F_KARR 9216                  // 64*72*2
#define F_STAGE (2 * F_KARR)         // 18432
#define F_SMEM (F_QARR + 2 * F_STAGE)   // 55296
#define NQT (TT / 128)               // 16

__global__ __launch_bounds__(256, 2) void flash_f16(
    const __half* __restrict__ qkv, __half* __restrict__ z16)
{
    extern __shared__ char fsmc[];
    const uint32_t sb = smem_u32(fsmc);
    const uint32_t sQ = sb;
    const uint32_t sKV = sb + F_QARR;

    const int h   = blockIdx.y;
    const int b   = blockIdx.z;
    const int tid = threadIdx.x;
    const int wid = tid >> 5;
    const int lid = tid & 31;
    const int g   = lid >> 2;
    const int tig = lid & 3;

    const uint32_t qOff = (uint32_t)(wid * 16 + (lid & 15)) * 144
                        + ((lid & 16) ? 16u : 0u);
    const uint32_t kOff = (uint32_t)((lid & 7) + ((lid & 16) ? 8 : 0)) * 144
                        + ((lid & 8) ? 16u : 0u);
    const uint32_t vRow = (uint32_t)((lid & 7) + ((lid & 8) ? 8 : 0)) * 144
                        + ((lid & 16) ? 16u : 0u);

#define F_LOADKV(kt, st) do {                                                  \
        const uint32_t kb_ = sKV + (st) * F_STAGE;                             \
        _Pragma("unroll")                                                      \
        for (int j_ = 0; j_ < 2; j_++) {                                       \
            const int idx_ = tid + 256 * j_;                                   \
            const int row_ = idx_ >> 3;                                        \
            const int ch_  = idx_ & 7;                                         \
            const size_t bk_ = (size_t)(b * TT + (kt) * 64 + row_) * QKV_N     \
                             + DD + h * HD + ch_ * 8;                          \
            const uint32_t d_ = (uint32_t)row_ * 144 + ch_ * 16;               \
            cp16(kb_ + d_,          qkv + bk_);                                \
            cp16(kb_ + F_KARR + d_, qkv + bk_ + DD);                           \
        }                                                                      \
    } while (0)

#pragma unroll 1
    for (int half = 0; half < 2; half++) {
        const int qt = half ? (int)blockIdx.x : (NQT - 1) - (int)blockIdx.x;
        const int q0  = qt * 128;
        const int nkv = 2 * qt + 2;
        const int qwmin = q0 + wid * 16;

        // Q cp.async (grouped with KV tile 0)
#pragma unroll
        for (int j = 0; j < 4; j++) {
            const int idx = tid + 256 * j;        // 0..1023
            const int row = idx >> 3;
            const int ch  = idx & 7;
            const size_t off = (size_t)(b * TT + q0 + row) * QKV_N + h * HD + ch * 8;
            cp16(sQ + (uint32_t)row * 144 + ch * 16, qkv + off);
        }

        F_LOADKV(0, 0); CP_COMMIT();
        F_LOADKV(1, 1); CP_COMMIT();

        float m_[2], l_[2], o_[8][4];
        m_[0] = m_[1] = -1e30f;
        l_[0] = l_[1] = 0.f;
#pragma unroll
        for (int ni = 0; ni < 8; ni++)
#pragma unroll
            for (int e = 0; e < 4; e++) o_[ni][e] = 0.f;

        for (int kt = 0; kt < nkv; kt++) {
            if (kt + 1 < nkv) { CP_WAIT1(); } else { CP_WAIT0(); }
            __syncthreads();

            const uint32_t st = sKV + (kt & 1) * F_STAGE;
            const uint32_t sK = st;
            const uint32_t sV = st + F_KARR;

            if (kt * 64 <= qwmin + 15) {
                // ---- S = Q K^T (fp16 single pass; Q pre-scaled) ----
                float s[8][4];
#pragma unroll
                for (int ni = 0; ni < 8; ni++)
#pragma unroll
                    for (int e = 0; e < 4; e++) s[ni][e] = 0.f;

#pragma unroll
                for (int k16 = 0; k16 < 4; k16++) {
                    const uint32_t kb = k16 * 32;
                    uint32_t q0r, q1r, q2r, q3r;
                    ldsm4(q0r, q1r, q2r, q3r, sQ + qOff + kb);
#pragma unroll
                    for (int nh = 0; nh < 4; nh++) {
                        uint32_t b0, b1, b2, b3;
                        ldsm4(b0, b1, b2, b3,
                              sK + kOff + (uint32_t)nh * 16 * 144 + kb);
                        mma_f16(s[2 * nh],     q0r, q1r, q2r, q3r, b0, b1);
                        mma_f16(s[2 * nh + 1], q0r, q1r, q2r, q3r, b2, b3);
                    }
                }

                if (kt * 64 + 63 > qwmin) {
#pragma unroll
                    for (int ni = 0; ni < 8; ni++)
#pragma unroll
                        for (int e = 0; e < 4; e++) {
                            const int qr = qwmin + g + ((e >= 2) ? 8 : 0);
                            const int kc = kt * 64 + ni * 8 + tig * 2 + (e & 1);
                            if (kc > qr) s[ni][e] = -1e30f;
                        }
                }

                // ---- online softmax ----
                float mx0 = s[0][0], mx1 = s[0][2];
#pragma unroll
                for (int ni = 0; ni < 8; ni++) {
                    mx0 = fmaxf(mx0, fmaxf(s[ni][0], s[ni][1]));
                    mx1 = fmaxf(mx1, fmaxf(s[ni][2], s[ni][3]));
                }
                mx0 = fmaxf(mx0, __shfl_xor_sync(0xffffffffu, mx0, 1));
                mx0 = fmaxf(mx0, __shfl_xor_sync(0xffffffffu, mx0, 2));
                mx1 = fmaxf(mx1, __shfl_xor_sync(0xffffffffu, mx1, 1));
                mx1 = fmaxf(mx1, __shfl_xor_sync(0xffffffffu, mx1, 2));

                const float mn0 = fmaxf(m_[0], mx0);
                const float mn1 = fmaxf(m_[1], mx1);
                const float al0 = __expf(m_[0] - mn0);
                const float al1 = __expf(m_[1] - mn1);

                float ps0 = 0.f, ps1 = 0.f;
#pragma unroll
                for (int ni = 0; ni < 8; ni++) {
                    s[ni][0] = __expf(s[ni][0] - mn0); ps0 += s[ni][0];
                    s[ni][1] = __expf(s[ni][1] - mn0); ps0 += s[ni][1];
                    s[ni][2] = __expf(s[ni][2] - mn1); ps1 += s[ni][2];
                    s[ni][3] = __expf(s[ni][3] - mn1); ps1 += s[ni][3];
                }
                ps0 += __shfl_xor_sync(0xffffffffu, ps0, 1);
                ps0 += __shfl_xor_sync(0xffffffffu, ps0, 2);
                ps1 += __shfl_xor_sync(0xffffffffu, ps1, 1);
                ps1 += __shfl_xor_sync(0xffffffffu, ps1, 2);

                l_[0] = l_[0] * al0 + ps0;
                l_[1] = l_[1] * al1 + ps1;
                m_[0] = mn0; m_[1] = mn1;
#pragma unroll
                for (int ni = 0; ni < 8; ni++) {
                    o_[ni][0] *= al0; o_[ni][1] *= al0;
                    o_[ni][2] *= al1; o_[ni][3] *= al1;
                }

                // ---- O += P V (fp16 single pass) ----
#pragma unroll
                for (int k16 = 0; k16 < 4; k16++) {
                    const int n0 = 2 * k16, n1 = 2 * k16 + 1;
                    const uint32_t p0 = packh2(s[n0][0], s[n0][1]);
                    const uint32_t p1 = packh2(s[n0][2], s[n0][3]);
                    const uint32_t p2 = packh2(s[n1][0], s[n1][1]);
                    const uint32_t p3 = packh2(s[n1][2], s[n1][3]);

                    const uint32_t rb = (uint32_t)k16 * 16 * 144;
#pragma unroll
                    for (int nh = 0; nh < 4; nh++) {
                        uint32_t v0, v1, v2, v3;
                        ldsm4t(v0, v1, v2, v3, sV + vRow + rb + (uint32_t)nh * 32);
                        mma_f16(o_[2 * nh],     p0, p1, p2, p3, v0, v1);
                        mma_f16(o_[2 * nh + 1], p0, p1, p2, p3, v2, v3);
                    }
                }
            }

            __syncthreads();
            if (kt + 2 < nkv) { F_LOADKV(kt + 2, (kt & 1)); CP_COMMIT(); }
        }

        // epilogue: normalize, write z fp16 (registers + gmem only)
        const float il0 = 1.f / l_[0];
        const float il1 = 1.f / l_[1];
        const size_t r0 = (size_t)(b * TT + q0 + wid * 16 + g);
#pragma unroll
        for (int ni = 0; ni < 8; ni++) {
            const int col = h * HD + ni * 8 + tig * 2;
            *(uint32_t*)&z16[r0 * DD + col] =
                packh2(o_[ni][0] * il0, o_[ni][1] * il0);
            *(uint32_t*)&z16[(r0 + 8) * DD + col] =
                packh2(o_[ni][2] * il1, o_[ni][3] * il1);
        }
    }
#undef F_LOADKV
}

// ---------------------------------------------------------------------------
extern "C" void kernel_launch(void* const* d_in, const int* in_sizes, int n_in,
                              void* d_out, int out_size)
{
    const float* X    = (const float*)d_in[0];
    const float* Wqkv = (const float*)d_in[1];
    const float* Wout = (const float*)d_in[2];
    float* out = (float*)d_out;

    __half *X16, *Wq16, *Wo16, *qkv16, *z16;
    cudaGetSymbolAddress((void**)&X16,   g_X16);
    cudaGetSymbolAddress((void**)&Wq16,  g_Wq16);
    cudaGetSymbolAddress((void**)&Wo16,  g_Wo16);
    cudaGetSymbolAddress((void**)&qkv16, g_qkv16);
    cudaGetSymbolAddress((void**)&z16,   g_z16);

    cudaFuncSetAttribute(gemm_f16<true>,
                         cudaFuncAttributeMaxDynamicSharedMemorySize, G_SMEM);
    cudaFuncSetAttribute(gemm_f16<false>,
                         cudaFuncAttributeMaxDynamicSharedMemorySize, G_SMEM);
    cudaFuncSetAttribute(flash_f16,
                         cudaFuncAttributeMaxDynamicSharedMemorySize, F_SMEM);

    // 0) one merged conversion sweep (q-rows of Wqkv pre-scaled by 1/8)
    convert_all<<<N4_ALL / 256, 256>>>(X, Wqkv, Wout, X16, Wq16, Wo16);

    // 1) qkv = X16 @ Wq16^T  (fp16x1) -> fp16, all 3072 cols
    gemm_f16<true><<<dim3(QKV_N / 128, M_ROWS / 128), 256, G_SMEM>>>(
        X16, Wq16, nullptr, qkv16, QKV_N);

    // 2) causal flash attention -> z fp16 (paired q-tiles, one balanced wave)
    flash_f16<<<dim3(NQT / 2, HH, BB), 256, F_SMEM>>>(qkv16, z16);

    // 3) out = z16 @ Wo16^T  (fp16x1) -> fp32
    gemm_f16<false><<<dim3(DD / 128, M_ROWS / 128), 256, G_SMEM>>>(
        z16, Wo16, out, nullptr, DD);
}

// round 16
// speedup vs baseline: 1.0784x; 1.0784x over previous
#include <cuda_runtime.h>
#include <cuda_bf16.h>
#include <cuda_fp16.h>
#include <cstdint>

// Problem constants
#define BB 2
#define TT 2048
#define DD 1024
#define HH 16
#define HD 64
#define M_ROWS 4096
#define QKV_N 3072
#define KDIM 1024

// ---------------------------------------------------------------------------
// Device-global scratch (allocation-free rule)
// ---------------------------------------------------------------------------
__device__ __half g_X16[(size_t)M_ROWS * KDIM];
__device__ __half g_Wq16[(size_t)QKV_N * KDIM];   // q rows pre-scaled by 1/8
__device__ __half g_Wo16[(size_t)DD * DD];
__device__ __half g_qkv16[(size_t)M_ROWS * QKV_N];  // q | k | v fp16
__device__ __half g_z16[(size_t)M_ROWS * DD];       // z fp16

// ---------------------------------------------------------------------------
// PTX helpers (baseline ISA: mma.sync sm_80, ldmatrix sm_75, cp.async sm_80)
// ---------------------------------------------------------------------------
__device__ __forceinline__ uint32_t smem_u32(const void* p) {
    uint32_t a;
    asm("{ .reg .u64 t; cvta.to.shared.u64 t, %1; cvt.u32.u64 %0, t; }"
        : "=r"(a) : "l"(p));
    return a;
}

__device__ __forceinline__ void cp16(uint32_t dst, const void* src) {
    asm volatile("cp.async.cg.shared.global [%0], [%1], 16;"
                 :: "r"(dst), "l"(src));
}
#define CP_COMMIT() asm volatile("cp.async.commit_group;" ::: "memory")
#define CP_WAIT1()  asm volatile("cp.async.wait_group 1;" ::: "memory")
#define CP_WAIT0()  asm volatile("cp.async.wait_group 0;" ::: "memory")

__device__ __forceinline__ void ldsm4(uint32_t& r0, uint32_t& r1, uint32_t& r2,
                                      uint32_t& r3, uint32_t addr) {
    asm volatile("ldmatrix.sync.aligned.m8n8.x4.shared.b16 {%0,%1,%2,%3}, [%4];"
                 : "=r"(r0), "=r"(r1), "=r"(r2), "=r"(r3) : "r"(addr));
}
__device__ __forceinline__ void ldsm4t(uint32_t& r0, uint32_t& r1, uint32_t& r2,
                                       uint32_t& r3, uint32_t addr) {
    asm volatile("ldmatrix.sync.aligned.m8n8.x4.trans.shared.b16 {%0,%1,%2,%3}, [%4];"
                 : "=r"(r0), "=r"(r1), "=r"(r2), "=r"(r3) : "r"(addr));
}

__device__ __forceinline__ void mma_f16(float* d, uint32_t a0, uint32_t a1,
                                        uint32_t a2, uint32_t a3,
                                        uint32_t b0, uint32_t b1)
{
    asm volatile(
        "mma.sync.aligned.m16n8k16.row.col.f32.f16.f16.f32 "
        "{%0,%1,%2,%3}, {%4,%5,%6,%7}, {%8,%9}, {%0,%1,%2,%3};"
        : "+f"(d[0]), "+f"(d[1]), "+f"(d[2]), "+f"(d[3])
        : "r"(a0), "r"(a1), "r"(a2), "r"(a3), "r"(b0), "r"(b1));
}

__device__ __forceinline__ uint32_t packh2(float x, float y)
{
    __half2 h = __floats2half2_rn(x, y);
    return *(uint32_t*)&h;
}

// ---------------------------------------------------------------------------
// Merged conversion kernel: X, Wqkv (q-rows pre-scaled by 1/8), Wout -> fp16
// ---------------------------------------------------------------------------
#define N4_X  (M_ROWS * KDIM / 4)       // 1048576
#define N4_WQ (QKV_N * KDIM / 4)        // 786432
#define N4_WO (DD * DD / 4)             // 262144
#define N4_QS (DD * KDIM / 4)           // 262144 (q out-feature rows of Wqkv)
#define N4_ALL (N4_X + N4_WQ + N4_WO)   // 2097152

__global__ void convert_all(const float* __restrict__ X,
                            const float* __restrict__ Wqkv,
                            const float* __restrict__ Wout,
                            __half* __restrict__ X16,
                            __half* __restrict__ Wq16,
                            __half* __restrict__ Wo16)
{
    const int i = blockIdx.x * blockDim.x + threadIdx.x;
    if (i < N4_X) {
        float4 v = ((const float4*)X)[i];
        ((uint2*)X16)[i] = make_uint2(packh2(v.x, v.y), packh2(v.z, v.w));
    } else if (i < N4_X + N4_WQ) {
        const int j = i - N4_X;
        float4 v = ((const float4*)Wqkv)[j];
        const float sc = (j < N4_QS) ? 0.125f : 1.0f;   // fold 1/sqrt(HD) into q
        ((uint2*)Wq16)[j] = make_uint2(packh2(v.x * sc, v.y * sc),
                                       packh2(v.z * sc, v.w * sc));
    } else {
        const int j = i - N4_X - N4_WQ;
        float4 v = ((const float4*)Wout)[j];
        ((uint2*)Wo16)[j] = make_uint2(packh2(v.x, v.y), packh2(v.z, v.w));
    }
}

// ===========================================================================
// fp16 single-pass GEMM NT: C = A16 * B16^T, K=1024.
// R13 chunk-64 tile kept EXACTLY; single-variable change: 3 smem stages +
// ONE __syncthreads per chunk (64 HMMA burst per sync, 16 syncs total).
// The sync at iter c proves compute of chunk c-1 is done in all warps;
// chunk c+2 lands in stage (c+2)%3 == (c-1)%3, so the load after the sync
// is hazard-free. Stage indices are increment-wrap (no modulo ALU).
// smem: 3 stages x (A,B [128][72] f16) = 110592 B; 2 CTAs/SM (216 KB/SM).
// ===========================================================================
#define H_ARR 18432                  // 128*72*2
#define H_STAGE (2 * H_ARR)          // 36864
#define H_SMEM (3 * H_STAGE)         // 110592
#define H_NCHUNK (KDIM / 64)         // 16

template<bool HALF_OUT>
__global__ __launch_bounds__(256, 2) void gemm_f16(
    const __half* __restrict__ Ag, const __half* __restrict__ Bg,
    float* __restrict__ Cf, __half* __restrict__ Chf, int N)
{
    extern __shared__ char hsm[];
    const uint32_t sb0 = smem_u32(hsm);

    const int tid = threadIdx.x;
    const int wid = tid >> 5;
    const int lid = tid & 31;
    const int g   = lid >> 2;
    const int tig = lid & 3;
    const int wm  = wid & 1;
    const int wn  = wid >> 1;
    const int bY  = blockIdx.y * 128;
    const int bX  = blockIdx.x * 128;

    const uint32_t aOff = (uint32_t)(wm * 64 + (lid & 15)) * 144
                        + ((lid & 16) ? 16u : 0u);
    const uint32_t bOff = (uint32_t)(wn * 32 + (lid & 7) + ((lid & 16) ? 8 : 0)) * 144
                        + ((lid & 8) ? 16u : 0u);

#define H_LOAD(c, st) do {                                                     \
        const uint32_t sb_ = sb0 + (st) * H_STAGE;                             \
        _Pragma("unroll")                                                      \
        for (int j_ = 0; j_ < 4; j_++) {                                       \
            const int idx_ = tid + 256 * j_;                                   \
            const int row_ = idx_ >> 3;                                        \
            const int ch_  = idx_ & 7;                                         \
            const uint32_t d_ = (uint32_t)row_ * 144 + ch_ * 16;               \
            cp16(sb_ + d_,         Ag + (size_t)(bY + row_) * KDIM + (c) * 64 + ch_ * 8); \
            cp16(sb_ + H_ARR + d_, Bg + (size_t)(bX + row_) * KDIM + (c) * 64 + ch_ * 8); \
        }                                                                      \
    } while (0)

    float acc[4][4][4];
#pragma unroll
    for (int mi = 0; mi < 4; mi++)
#pragma unroll
        for (int ni = 0; ni < 4; ni++)
#pragma unroll
            for (int r = 0; r < 4; r++) acc[mi][ni][r] = 0.f;

    H_LOAD(0, 0); CP_COMMIT();
    H_LOAD(1, 1); CP_COMMIT();

    int ld_st = 2;       // stage for the next issued load
    int cp_st = 0;       // stage holding the chunk to compute
    for (int c = 0; c < H_NCHUNK; c++) {
        if (c + 1 < H_NCHUNK) { CP_WAIT1(); } else { CP_WAIT0(); }
        __syncthreads();   // chunk c visible; compute of c-1 done in all warps

        if (c + 2 < H_NCHUNK) {
            H_LOAD(c + 2, ld_st);
            CP_COMMIT();
            ld_st = (ld_st == 2) ? 0 : ld_st + 1;
        }

        const uint32_t sb = sb0 + (uint32_t)cp_st * H_STAGE;
        cp_st = (cp_st == 2) ? 0 : cp_st + 1;
#pragma unroll
        for (int k16 = 0; k16 < 4; k16++) {
            const uint32_t kb = k16 * 32;
            const uint32_t bBase = sb + H_ARR + bOff + kb;
            uint32_t bf_[2][4];
            ldsm4(bf_[0][0], bf_[0][1], bf_[0][2], bf_[0][3], bBase);
            ldsm4(bf_[1][0], bf_[1][1], bf_[1][2], bf_[1][3], bBase + 16 * 144);
#pragma unroll
            for (int mi = 0; mi < 4; mi++) {
                uint32_t a0, a1, a2, a3;
                ldsm4(a0, a1, a2, a3, sb + aOff + kb + (uint32_t)mi * 16 * 144);
#pragma unroll
                for (int ni = 0; ni < 4; ni++)
                    mma_f16(acc[mi][ni], a0, a1, a2, a3,
                            bf_[ni >> 1][(ni & 1) * 2],
                            bf_[ni >> 1][(ni & 1) * 2 + 1]);
            }
        }
    }

#pragma unroll
    for (int mi = 0; mi < 4; mi++) {
        const int r0 = bY + wm * 64 + mi * 16 + g;
#pragma unroll
        for (int ni = 0; ni < 4; ni++) {
            const int c0 = bX + wn * 32 + ni * 8 + tig * 2;
            if (HALF_OUT) {
                *(uint32_t*)&Chf[(size_t)r0 * N + c0] =
                    packh2(acc[mi][ni][0], acc[mi][ni][1]);
                *(uint32_t*)&Chf[(size_t)(r0 + 8) * N + c0] =
                    packh2(acc[mi][ni][2], acc[mi][ni][3]);
            } else {
                float2 v0; v0.x = acc[mi][ni][0]; v0.y = acc[mi][ni][1];
                float2 v1; v1.x = acc[mi][ni][2]; v1.y = acc[mi][ni][3];
                *(float2*)(Cf + (size_t)r0 * N + c0)       = v0;
                *(float2*)(Cf + (size_t)(r0 + 8) * N + c0) = v1;
            }
        }
    }
#undef H_LOAD
}

// ===========================================================================
// Flash attention (unchanged from passing round-13 kernel): all fp16
// single-pass, paired q-tiles (qt = 15-i then i -> 34 kv units per CTA),
// grid 8x16x2 = one balanced wave at 2 CTAs/SM. Q pre-scaled by 1/8.
// smem: Q[128][72] f16 + 2 stages x (K,V [64][72] f16) = 55296 B.
// ===========================================================================
#define F_QARR 18432                 // 128*72*2
#define F_KARR 9216                  // 64*72*2
#define F_STAGE (2 * F_KARR)         // 18432
#define F_SMEM (F_QARR + 2 * F_STAGE)   // 55296
#define NQT (TT / 128)               // 16

__global__ __launch_bounds__(256, 2) void flash_f16(
    const __half* __restrict__ qkv, __half* __restrict__ z16)
{
    extern __shared__ char fsmc[];
    const uint32_t sb = smem_u32(fsmc);
    const uint32_t sQ = sb;
    const uint32_t sKV = sb + F_QARR;

    const int h   = blockIdx.y;
    const int b   = blockIdx.z;
    const int tid = threadIdx.x;
    const int wid = tid >> 5;
    const int lid = tid & 31;
    const int g   = lid >> 2;
    const int tig = lid & 3;

    const uint32_t qOff = (uint32_t)(wid * 16 + (lid & 15)) * 144
                        + ((lid & 16) ? 16u : 0u);
    const uint32_t kOff = (uint32_t)((lid & 7) + ((lid & 16) ? 8 : 0)) * 144
                        + ((lid & 8) ? 16u : 0u);
    const uint32_t vRow = (uint32_t)((lid & 7) + ((lid & 8) ? 8 : 0)) * 144
                        + ((lid & 16) ? 16u : 0u);

#define F_LOADKV(kt, st) do {                                                  \
        const uint32_t kb_ = sKV + (st) * F_STAGE;                             \
        _Pragma("unroll")                                                      \
        for (int j_ = 0; j_ < 2; j_++) {                                       \
            const int idx_ = tid + 256 * j_;                                   \
            const int row_ = idx_ >> 3;                                        \
            const int ch_  = idx_ & 7;                                         \
            const size_t bk_ = (size_t)(b * TT + (kt) * 64 + row_) * QKV_N     \
                             + DD + h * HD + ch_ * 8;                          \
            const uint32_t d_ = (uint32_t)row_ * 144 + ch_ * 16;               \
            cp16(kb_ + d_,          qkv + bk_);                                \
            cp16(kb_ + F_KARR + d_, qkv + bk_ + DD);                           \
        }                                                                      \
    } while (0)

#pragma unroll 1
    for (int half = 0; half < 2; half++) {
        const int qt = half ? (int)blockIdx.x : (NQT - 1) - (int)blockIdx.x;
        const int q0  = qt * 128;
        const int nkv = 2 * qt + 2;
        const int qwmin = q0 + wid * 16;

        // Q cp.async (grouped with KV tile 0)
#pragma unroll
        for (int j = 0; j < 4; j++) {
            const int idx = tid + 256 * j;        // 0..1023
            const int row = idx >> 3;
            const int ch  = idx & 7;
            const size_t off = (size_t)(b * TT + q0 + row) * QKV_N + h * HD + ch * 8;
            cp16(sQ + (uint32_t)row * 144 + ch * 16, qkv + off);
        }

        F_LOADKV(0, 0); CP_COMMIT();
        F_LOADKV(1, 1); CP_COMMIT();

        float m_[2], l_[2], o_[8][4];
        m_[0] = m_[1] = -1e30f;
        l_[0] = l_[1] = 0.f;
#pragma unroll
        for (int ni = 0; ni < 8; ni++)
#pragma unroll
            for (int e = 0; e < 4; e++) o_[ni][e] = 0.f;

        for (int kt = 0; kt < nkv; kt++) {
            if (kt + 1 < nkv) { CP_WAIT1(); } else { CP_WAIT0(); }
            __syncthreads();

            const uint32_t st = sKV + (kt & 1) * F_STAGE;
            const uint32_t sK = st;
            const uint32_t sV = st + F_KARR;

            if (kt * 64 <= qwmin + 15) {
                // ---- S = Q K^T (fp16 single pass; Q pre-scaled) ----
                float s[8][4];
#pragma unroll
                for (int ni = 0; ni < 8; ni++)
#pragma unroll
                    for (int e = 0; e < 4; e++) s[ni][e] = 0.f;

#pragma unroll
                for (int k16 = 0; k16 < 4; k16++) {
                    const uint32_t kb = k16 * 32;
                    uint32_t q0r, q1r, q2r, q3r;
                    ldsm4(q0r, q1r, q2r, q3r, sQ + qOff + kb);
#pragma unroll
                    for (int nh = 0; nh < 4; nh++) {
                        uint32_t b0, b1, b2, b3;
                        ldsm4(b0, b1, b2, b3,
                              sK + kOff + (uint32_t)nh * 16 * 144 + kb);
                        mma_f16(s[2 * nh],     q0r, q1r, q2r, q3r, b0, b1);
                        mma_f16(s[2 * nh + 1], q0r, q1r, q2r, q3r, b2, b3);
                    }
                }

                if (kt * 64 + 63 > qwmin) {
#pragma unroll
                    for (int ni = 0; ni < 8; ni++)
#pragma unroll
                        for (int e = 0; e < 4; e++) {
                            const int qr = qwmin + g + ((e >= 2) ? 8 : 0);
                            const int kc = kt * 64 + ni * 8 + tig * 2 + (e & 1);
                            if (kc > qr) s[ni][e] = -1e30f;
                        }
                }

                // ---- online softmax ----
                float mx0 = s[0][0], mx1 = s[0][2];
#pragma unroll
                for (int ni = 0; ni < 8; ni++) {
                    mx0 = fmaxf(mx0, fmaxf(s[ni][0], s[ni][1]));
                    mx1 = fmaxf(mx1, fmaxf(s[ni][2], s[ni][3]));
                }
                mx0 = fmaxf(mx0, __shfl_xor_sync(0xffffffffu, mx0, 1));
                mx0 = fmaxf(mx0, __shfl_xor_sync(0xffffffffu, mx0, 2));
                mx1 = fmaxf(mx1, __shfl_xor_sync(0xffffffffu, mx1, 1));
                mx1 = fmaxf(mx1, __shfl_xor_sync(0xffffffffu, mx1, 2));

                const float mn0 = fmaxf(m_[0], mx0);
                const float mn1 = fmaxf(m_[1], mx1);
                const float al0 = __expf(m_[0] - mn0);
                const float al1 = __expf(m_[1] - mn1);

                float ps0 = 0.f, ps1 = 0.f;
#pragma unroll
                for (int ni = 0; ni < 8; ni++) {
                    s[ni][0] = __expf(s[ni][0] - mn0); ps0 += s[ni][0];
                    s[ni][1] = __expf(s[ni][1] - mn0); ps0 += s[ni][1];
                    s[ni][2] = __expf(s[ni][2] - mn1); ps1 += s[ni][2];
                    s[ni][3] = __expf(s[ni][3] - mn1); ps1 += s[ni][3];
                }
                ps0 += __shfl_xor_sync(0xffffffffu, ps0, 1);
                ps0 += __shfl_xor_sync(0xffffffffu, ps0, 2);
                ps1 += __shfl_xor_sync(0xffffffffu, ps1, 1);
                ps1 += __shfl_xor_sync(0xffffffffu, ps1, 2);

                l_[0] = l_[0] * al0 + ps0;
                l_[1] = l_[1] * al1 + ps1;
                m_[0] = mn0; m_[1] = mn1;
#pragma unroll
                for (int ni = 0; ni < 8; ni++) {
                    o_[ni][0] *= al0; o_[ni][1] *= al0;
                    o_[ni][2] *= al1; o_[ni][3] *= al1;
                }

                // ---- O += P V (fp16 single pass) ----
#pragma unroll
                for (int k16 = 0; k16 < 4; k16++) {
                    const int n0 = 2 * k16, n1 = 2 * k16 + 1;
                    const uint32_t p0 = packh2(s[n0][0], s[n0][1]);
                    const uint32_t p1 = packh2(s[n0][2], s[n0][3]);
                    const uint32_t p2 = packh2(s[n1][0], s[n1][1]);
                    const uint32_t p3 = packh2(s[n1][2], s[n1][3]);

                    const uint32_t rb = (uint32_t)k16 * 16 * 144;
#pragma unroll
                    for (int nh = 0; nh < 4; nh++) {
                        uint32_t v0, v1, v2, v3;
                        ldsm4t(v0, v1, v2, v3, sV + vRow + rb + (uint32_t)nh * 32);
                        mma_f16(o_[2 * nh],     p0, p1, p2, p3, v0, v1);
                        mma_f16(o_[2 * nh + 1], p0, p1, p2, p3, v2, v3);
                    }
                }
            }

            __syncthreads();
            if (kt + 2 < nkv) { F_LOADKV(kt + 2, (kt & 1)); CP_COMMIT(); }
        }

        // epilogue: normalize, write z fp16 (registers + gmem only)
        const float il0 = 1.f / l_[0];
        const float il1 = 1.f / l_[1];
        const size_t r0 = (size_t)(b * TT + q0 + wid * 16 + g);
#pragma unroll
        for (int ni = 0; ni < 8; ni++) {
            const int col = h * HD + ni * 8 + tig * 2;
            *(uint32_t*)&z16[r0 * DD + col] =
                packh2(o_[ni][0] * il0, o_[ni][1] * il0);
            *(uint32_t*)&z16[(r0 + 8) * DD + col] =
                packh2(o_[ni][2] * il1, o_[ni][3] * il1);
        }
    }
#undef F_LOADKV
}

// ---------------------------------------------------------------------------
extern "C" void kernel_launch(void* const* d_in, const int* in_sizes, int n_in,
                              void* d_out, int out_size)
{
    const float* X    = (const float*)d_in[0];
    const float* Wqkv = (const float*)d_in[1];
    const float* Wout = (const float*)d_in[2];
    float* out = (float*)d_out;

    __half *X16, *Wq16, *Wo16, *qkv16, *z16;
    cudaGetSymbolAddress((void**)&X16,   g_X16);
    cudaGetSymbolAddress((void**)&Wq16,  g_Wq16);
    cudaGetSymbolAddress((void**)&Wo16,  g_Wo16);
    cudaGetSymbolAddress((void**)&qkv16, g_qkv16);
    cudaGetSymbolAddress((void**)&z16,   g_z16);

    cudaFuncSetAttribute(gemm_f16<true>,
                         cudaFuncAttributeMaxDynamicSharedMemorySize, H_SMEM);
    cudaFuncSetAttribute(gemm_f16<false>,
                         cudaFuncAttributeMaxDynamicSharedMemorySize, H_SMEM);
    cudaFuncSetAttribute(flash_f16,
                         cudaFuncAttributeMaxDynamicSharedMemorySize, F_SMEM);

    // 0) one merged conversion sweep (q-rows of Wqkv pre-scaled by 1/8)
    convert_all<<<N4_ALL / 256, 256>>>(X, Wqkv, Wout, X16, Wq16, Wo16);

    // 1) qkv = X16 @ Wq16^T  (fp16x1) -> fp16, all 3072 cols
    gemm_f16<true><<<dim3(QKV_N / 128, M_ROWS / 128), 256, H_SMEM>>>(
        X16, Wq16, nullptr, qkv16, QKV_N);

    // 2) causal flash attention -> z fp16 (paired q-tiles, one balanced wave)
    flash_f16<<<dim3(NQT / 2, HH, BB), 256, F_SMEM>>>(qkv16, z16);

    // 3) out = z16 @ Wo16^T  (fp16x1) -> fp32
    gemm_f16<false><<<dim3(DD / 128, M_ROWS / 128), 256, H_SMEM>>>(
        z16, Wo16, out, nullptr, DD);
}